// round 3
// baseline (speedup 1.0000x reference)
#include <cuda_runtime.h>
#include <cuda_bf16.h>
#include <math.h>

#define Nn 100000
#define Ee 1600000
#define Gg 64

// ---------------- packed f32x2 helpers ----------------
#define PACK2(out, a, b) \
    asm("mov.b64 %0, {%1, %2};" : "=l"(out) : "f"(a), "f"(b))
#define FMA2(acc, a, b) \
    asm("fma.rn.f32x2 %0, %1, %2, %0;" : "+l"(acc) : "l"(a), "l"(b))
#define MUL2(out, a, b) \
    asm("mul.rn.f32x2 %0, %1, %2;" : "=l"(out) : "l"(a), "l"(b))

// ---------------- device scratch (static, no runtime allocation) ----------------
__device__ int   g_cnt[Nn];
__device__ int   g_rowptr[Nn + 1];
__device__ int   g_cursor[Nn];
__device__ int   g_cols[Ee];
__device__ float g_dis[Nn];
__device__ float g_bufA[Nn * 64];
__device__ float g_bufB[Nn * 64];
__device__ float g_stats[3 * 128];      // per layer: [0..H) sum, [H..2H) sumsq
__device__ int   g_bsum[256];           // scan partials
__device__ float g_pool[Gg * 33];       // per graph: sum[16], max[16], count

// ---------------- small utility kernels ----------------
__global__ void k_zero() {
    int i = blockIdx.x * 256 + threadIdx.x;
    if (i < Nn) g_cnt[i] = 0;
    if (i < 3 * 128) g_stats[i] = 0.f;
}
__global__ void k_hist(const int* __restrict__ dst) {
    int e = blockIdx.x * 256 + threadIdx.x;
    if (e < Ee) atomicAdd(&g_cnt[dst[e]], 1);
}
__global__ void k_dis() {
    int i = blockIdx.x * 256 + threadIdx.x;
    if (i < Nn) g_dis[i] = rsqrtf((float)(g_cnt[i] + 1));
}

#define SCAN_NB 196   // 196 * 512 = 100352 >= Nn

__global__ void k_scan1() {
    __shared__ int sh[512];
    int t = threadIdx.x, idx = blockIdx.x * 512 + t;
    sh[t] = (idx < Nn) ? g_cnt[idx] : 0;
    __syncthreads();
    for (int off = 256; off > 0; off >>= 1) {
        if (t < off) sh[t] += sh[t + off];
        __syncthreads();
    }
    if (t == 0) g_bsum[blockIdx.x] = sh[0];
}
__global__ void k_scan2() {
    __shared__ int sh[256];
    int t = threadIdx.x;
    int v = (t < SCAN_NB) ? g_bsum[t] : 0;
    sh[t] = v;
    __syncthreads();
    for (int off = 1; off < 256; off <<= 1) {
        int add = (t >= off) ? sh[t - off] : 0;
        __syncthreads();
        sh[t] += add;
        __syncthreads();
    }
    if (t < SCAN_NB) g_bsum[t] = sh[t] - v;   // exclusive
    if (t == 0) g_rowptr[Nn] = Ee;
}
__global__ void k_scan3() {
    __shared__ int sh[512];
    int t = threadIdx.x, idx = blockIdx.x * 512 + t;
    int v = (idx < Nn) ? g_cnt[idx] : 0;
    sh[t] = v;
    __syncthreads();
    for (int off = 1; off < 512; off <<= 1) {
        int add = (t >= off) ? sh[t - off] : 0;
        __syncthreads();
        sh[t] += add;
        __syncthreads();
    }
    if (idx < Nn) {
        int ex = g_bsum[blockIdx.x] + sh[t] - v;
        g_rowptr[idx] = ex;
        g_cursor[idx] = ex;
    }
}
__global__ void k_fill(const int* __restrict__ src, const int* __restrict__ dst) {
    int e = blockIdx.x * 256 + threadIdx.x;
    if (e < Ee) {
        int d = dst[e];
        int p = atomicAdd(&g_cursor[d], 1);
        g_cols[p] = src[e];
    }
}

// ---------------- GEMM (broadcast scheme, packed f32x2 FMA) ----------------
// out[i,c] = dis[i] * sum_k f(h[i,k]) * W[k,c]
// f = identity (NORM=false) or BN-normalize + leaky relu (NORM=true).
// block = 128 threads = 128 nodes; one lane per node; acc[H] packed in 64-bit regs;
// W resident in smem, read as warp-uniform 128-bit broadcasts.
template <int K, int H, bool NORM>
__global__ void __launch_bounds__(128, 4) k_gemm(const float* __restrict__ h,
                                                 const float* __restrict__ W,
                                                 const float* __restrict__ stats,
                                                 const float* __restrict__ gamma,
                                                 const float* __restrict__ beta,
                                                 float* __restrict__ out) {
    __shared__ float Wsm[K * H];
    __shared__ float xs[128 * 17];
    __shared__ float nsc[K], nsh[K];
    const int tid = threadIdx.x;
    const int base = blockIdx.x * 128;
    const int node = base + tid;

    // load full W into smem
    {
        const float4* Wg = reinterpret_cast<const float4*>(W);
        float4* Ws = reinterpret_cast<float4*>(Wsm);
#pragma unroll
        for (int i = tid; i < K * H / 4; i += 128) Ws[i] = Wg[i];
    }
    if (NORM) {
        for (int c = tid; c < K; c += 128) {
            float m = stats[c] * (1.0f / Nn);
            float var = stats[K + c] * (1.0f / Nn) - m * m;
            float rstd = rsqrtf(var + 1e-5f);
            float sc = rstd * gamma[c];
            nsc[c] = sc;
            nsh[c] = beta[c] - m * sc;
        }
    }
    __syncthreads();

    unsigned long long acc2[H / 2];
#pragma unroll
    for (int j = 0; j < H / 2; j++) acc2[j] = 0ull;

    for (int kc = 0; kc < K; kc += 16) {
        // stage x chunk [128 nodes][16 cols] into padded smem (with fused BN+lrelu)
#pragma unroll
        for (int jj = 0; jj < 4; jj++) {
            int f = tid + 128 * jj;          // 0..511 float4 slots
            int row = f >> 2, c4 = f & 3;
            int grow = base + row;
            float4 v = make_float4(0.f, 0.f, 0.f, 0.f);
            if (grow < Nn)
                v = *reinterpret_cast<const float4*>(h + (size_t)grow * K + kc + c4 * 4);
            if (NORM) {
                int cb = kc + c4 * 4;
                v.x = v.x * nsc[cb + 0] + nsh[cb + 0]; v.x = v.x > 0.f ? v.x : 0.1f * v.x;
                v.y = v.y * nsc[cb + 1] + nsh[cb + 1]; v.y = v.y > 0.f ? v.y : 0.1f * v.y;
                v.z = v.z * nsc[cb + 2] + nsh[cb + 2]; v.z = v.z > 0.f ? v.z : 0.1f * v.z;
                v.w = v.w * nsc[cb + 3] + nsh[cb + 3]; v.w = v.w > 0.f ? v.w : 0.1f * v.w;
            }
            float* d = &xs[row * 17 + c4 * 4];
            d[0] = v.x; d[1] = v.y; d[2] = v.z; d[3] = v.w;
        }
        __syncthreads();
#pragma unroll
        for (int kk = 0; kk < 16; kk++) {
            float xv = xs[tid * 17 + kk];
            unsigned long long xx;
            PACK2(xx, xv, xv);
            const ulonglong2* w2 = reinterpret_cast<const ulonglong2*>(&Wsm[(kc + kk) * H]);
#pragma unroll
            for (int j = 0; j < H / 4; j++) {
                ulonglong2 w = w2[j];
                FMA2(acc2[2 * j + 0], xx, w.x);
                FMA2(acc2[2 * j + 1], xx, w.y);
            }
        }
        __syncthreads();
    }
    if (node < Nn) {
        float dn = g_dis[node];
        unsigned long long dd;
        PACK2(dd, dn, dn);
        ulonglong2* o = reinterpret_cast<ulonglong2*>(out + (size_t)node * H);
#pragma unroll
        for (int j = 0; j < H / 4; j++) {
            unsigned long long r0, r1;
            MUL2(r0, acc2[2 * j + 0], dd);
            MUL2(r1, acc2[2 * j + 1], dd);
            o[j] = make_ulonglong2(r0, r1);
        }
    }
}

// ---------------- gather: pre[i] = dis[i]*(hws[i] + sum_{e:dst=i} hws[src]) + b ----
// pair-packed: lane owns 2 adjacent channels (float2 loads); for H<64 a warp
// processes 32/(H/2) neighbors concurrently, combined via shfl butterfly.
// Fused BN sum/sumsq accumulation.
template <int H>
__global__ void __launch_bounds__(256) k_gather(const float* __restrict__ hws,
                                                const float* __restrict__ b,
                                                float* __restrict__ pre,
                                                float* __restrict__ stats) {
    constexpr int LPN = H / 2;        // lanes per neighbor
    constexpr int GPW = 32 / LPN;     // neighbor groups per warp
    const int lane = threadIdx.x & 31;
    const int grp = lane / LPN;
    const int cp = lane % LPN;        // channel-pair index
    const int c0 = 2 * cp;
    const int warp = (blockIdx.x * blockDim.x + threadIdx.x) >> 5;
    const int nwarps = (gridDim.x * blockDim.x) >> 5;

    float2 bia = *reinterpret_cast<const float2*>(b + c0);

    float sx = 0.f, sy = 0.f, qx = 0.f, qy = 0.f;   // BN stats (grp 0 lanes)

    for (int node = warp; node < Nn; node += nwarps) {
        int r0 = g_rowptr[node], r1 = g_rowptr[node + 1];
        float ax0 = 0.f, ay0 = 0.f, ax1 = 0.f, ay1 = 0.f;
        int p = r0 + grp;
        for (; p + 3 * GPW < r1; p += 4 * GPW) {
            int s0 = g_cols[p];
            int s1 = g_cols[p + GPW];
            int s2 = g_cols[p + 2 * GPW];
            int s3 = g_cols[p + 3 * GPW];
            float2 v0 = *reinterpret_cast<const float2*>(hws + (size_t)s0 * H + c0);
            float2 v1 = *reinterpret_cast<const float2*>(hws + (size_t)s1 * H + c0);
            float2 v2 = *reinterpret_cast<const float2*>(hws + (size_t)s2 * H + c0);
            float2 v3 = *reinterpret_cast<const float2*>(hws + (size_t)s3 * H + c0);
            ax0 += v0.x + v2.x; ay0 += v0.y + v2.y;
            ax1 += v1.x + v3.x; ay1 += v1.y + v3.y;
        }
        for (; p < r1; p += GPW) {
            int s = g_cols[p];
            float2 v = *reinterpret_cast<const float2*>(hws + (size_t)s * H + c0);
            ax0 += v.x; ay0 += v.y;
        }
        float ax = ax0 + ax1, ay = ay0 + ay1;
        // combine neighbor groups
#pragma unroll
        for (int off = LPN; off < 32; off <<= 1) {
            ax += __shfl_xor_sync(0xffffffffu, ax, off);
            ay += __shfl_xor_sync(0xffffffffu, ay, off);
        }
        if (grp == 0) {
            float2 self = *reinterpret_cast<const float2*>(hws + (size_t)node * H + c0);
            float dn = g_dis[node];
            float vx = dn * (ax + self.x) + bia.x;
            float vy = dn * (ay + self.y) + bia.y;
            *reinterpret_cast<float2*>(pre + (size_t)node * H + c0) = make_float2(vx, vy);
            sx += vx; sy += vy;
            qx += vx * vx; qy += vy * vy;
        }
    }
    if (grp == 0) {
        atomicAdd(&stats[c0], sx);
        atomicAdd(&stats[c0 + 1], sy);
        atomicAdd(&stats[H + c0], qx);
        atomicAdd(&stats[H + c0 + 1], qy);
    }
}

// ---------------- pooling: per-graph sum/max/count over normalized x3 [N,16] ----------------
__device__ __forceinline__ int lower_bound_batch(const int* __restrict__ batch, int g) {
    int lo = 0, hi = Nn;
    while (lo < hi) {
        int m = (lo + hi) >> 1;
        if (batch[m] < g) lo = m + 1; else hi = m;
    }
    return lo;
}

__global__ void k_pool(const float* __restrict__ x3, const int* __restrict__ batch,
                       const float* __restrict__ stats,
                       const float* __restrict__ gamma, const float* __restrict__ beta) {
    __shared__ int ss, se;
    __shared__ float ssum[256], smax[256];
    int g = blockIdx.x, t = threadIdx.x;
    if (t == 0) { ss = lower_bound_batch(batch, g); se = lower_bound_batch(batch, g + 1); }
    __syncthreads();
    int s = ss, e = se;
    int c = t & 15;
    // per-channel BN scale/shift (layer 3)
    float m = stats[c] * (1.0f / Nn);
    float var = stats[16 + c] * (1.0f / Nn) - m * m;
    float rstd = rsqrtf(var + 1e-5f);
    float sc = rstd * gamma[c];
    float sh = beta[c] - m * sc;

    float sum = 0.f, mx = -3.402823466e+38f;
    for (int r = s + (t >> 4); r < e; r += 16) {
        float v = x3[r * 16 + c] * sc + sh;
        v = v > 0.f ? v : 0.1f * v;
        sum += v;
        mx = fmaxf(mx, v);
    }
    ssum[t] = sum; smax[t] = mx;
    __syncthreads();
    for (int off = 128; off >= 16; off >>= 1) {
        if (t < off) { ssum[t] += ssum[t + off]; smax[t] = fmaxf(smax[t], smax[t + off]); }
        __syncthreads();
    }
    if (t < 16) { g_pool[g * 33 + t] = ssum[t]; g_pool[g * 33 + 16 + t] = smax[t]; }
    if (t == 0) g_pool[g * 33 + 32] = (float)(e - s);
}

// ---------------- head: attention pooling + MLP + sigmoid ----------------
__global__ void k_head(const float* __restrict__ attn_w, const float* __restrict__ attn_b,
                       const float* __restrict__ fc1_w, const float* __restrict__ fc1_b,
                       const float* __restrict__ fc2_w, const float* __restrict__ fc2_b,
                       const float* __restrict__ out_w, const float* __restrict__ out_b,
                       float* __restrict__ out) {
    int g = threadIdx.x;
    if (g >= Gg) return;
    float sm[16], mx[16], mean[16];
    float cnt = g_pool[g * 33 + 32];
    float inv = 1.0f / fmaxf(cnt, 1.0f);
#pragma unroll
    for (int k = 0; k < 16; k++) {
        sm[k] = g_pool[g * 33 + k];
        mx[k] = g_pool[g * 33 + 16 + k];
        mean[k] = sm[k] * inv;
    }
    float z[3];
#pragma unroll
    for (int j = 0; j < 3; j++) z[j] = attn_b[j];
#pragma unroll
    for (int k = 0; k < 16; k++) {
#pragma unroll
        for (int j = 0; j < 3; j++) {
            z[j] += mean[k] * attn_w[k * 3 + j]
                  + mx[k]   * attn_w[(16 + k) * 3 + j]
                  + sm[k]   * attn_w[(32 + k) * 3 + j];
        }
    }
    float zm = fmaxf(z[0], fmaxf(z[1], z[2]));
    float e0 = expf(z[0] - zm), e1 = expf(z[1] - zm), e2 = expf(z[2] - zm);
    float is = 1.f / (e0 + e1 + e2);
    float a0 = e0 * is, a1 = e1 * is, a2 = e2 * is;
    float xg[16];
#pragma unroll
    for (int k = 0; k < 16; k++) xg[k] = a0 * mean[k] + a1 * mx[k] + a2 * sm[k];
    float y1[16];
#pragma unroll
    for (int j = 0; j < 16; j++) {
        float acc = fc1_b[j];
#pragma unroll
        for (int k = 0; k < 16; k++) acc += xg[k] * fc1_w[k * 16 + j];
        y1[j] = acc > 0.f ? acc : 0.1f * acc;
    }
    float y2[8];
#pragma unroll
    for (int j = 0; j < 8; j++) {
        float acc = fc2_b[j];
#pragma unroll
        for (int k = 0; k < 16; k++) acc += y1[k] * fc2_w[k * 8 + j];
        y2[j] = acc > 0.f ? acc : 0.1f * acc;
    }
    float o = out_b[0];
#pragma unroll
    for (int k = 0; k < 8; k++) o += y2[k] * out_w[k];
    out[g] = 1.f / (1.f + expf(-o));
}

// ---------------- host launch ----------------
extern "C" void kernel_launch(void* const* d_in, const int* in_sizes, int n_in,
                              void* d_out, int out_size) {
    const float* x      = (const float*)d_in[0];
    const float* W1     = (const float*)d_in[1];
    const float* b1     = (const float*)d_in[2];
    const float* W2     = (const float*)d_in[3];
    const float* b2     = (const float*)d_in[4];
    const float* W3     = (const float*)d_in[5];
    const float* b3     = (const float*)d_in[6];
    const float* g1     = (const float*)d_in[7];
    const float* be1    = (const float*)d_in[8];
    const float* g2     = (const float*)d_in[9];
    const float* be2    = (const float*)d_in[10];
    const float* g3     = (const float*)d_in[11];
    const float* be3    = (const float*)d_in[12];
    const float* attn_w = (const float*)d_in[13];
    const float* attn_b = (const float*)d_in[14];
    const float* fc1_w  = (const float*)d_in[15];
    const float* fc1_b  = (const float*)d_in[16];
    const float* fc2_w  = (const float*)d_in[17];
    const float* fc2_b  = (const float*)d_in[18];
    const float* out_w  = (const float*)d_in[19];
    const float* out_b  = (const float*)d_in[20];
    const int*   ei     = (const int*)d_in[21];
    const int*   batch  = (const int*)d_in[22];

    const int* src = ei;
    const int* dst = ei + Ee;
    float* out = (float*)d_out;

    void *pA = nullptr, *pB = nullptr, *pS = nullptr;
    cudaGetSymbolAddress(&pA, g_bufA);
    cudaGetSymbolAddress(&pB, g_bufB);
    cudaGetSymbolAddress(&pS, g_stats);
    float* bufA = (float*)pA;
    float* bufB = (float*)pB;
    float* st0 = (float*)pS;          // layer1 stats (sum[64], sq[64])
    float* st1 = st0 + 128;           // layer2 stats (sum[32], sq[32])
    float* st2 = st0 + 256;           // layer3 stats (sum[16], sq[16])

    const int gemm_grid = (Nn + 127) / 128;   // 782
    const int gather_grid = 1184;             // 148 SMs * 8 blocks

    // degree + dis first, so GEMM1 can run before the scan chain
    k_zero<<<(Nn + 255) / 256, 256>>>();                       // 0
    k_hist<<<(Ee + 255) / 256, 256>>>(dst);                    // 1
    k_dis<<<(Nn + 255) / 256, 256>>>();                        // 2
    k_gemm<128, 64, false><<<gemm_grid, 128>>>(x, W1, nullptr, nullptr, nullptr, bufA); // 3 (profiled slot)
    k_scan1<<<SCAN_NB, 512>>>();                               // 4
    k_scan2<<<1, 256>>>();                                     // 5
    k_scan3<<<SCAN_NB, 512>>>();                               // 6
    k_fill<<<(Ee + 255) / 256, 256>>>(src, dst);               // 7

    // Layer 1 aggregate
    k_gather<64><<<gather_grid, 256>>>(bufA, b1, bufB, st0);   // 8

    // Layer 2: 64 -> 32 (BN1 + lrelu fused into GEMM load)
    k_gemm<64, 32, true><<<gemm_grid, 128>>>(bufB, W2, st0, g1, be1, bufA);   // 9
    k_gather<32><<<gather_grid, 256>>>(bufA, b2, bufB, st1);   // 10

    // Layer 3: 32 -> 16 (BN2 + lrelu fused into GEMM load)
    k_gemm<32, 16, true><<<gemm_grid, 128>>>(bufB, W3, st1, g2, be2, bufA);   // 11
    k_gather<16><<<gather_grid, 256>>>(bufA, b3, bufB, st2);   // 12

    // Pool (BN3 + lrelu fused) + head
    k_pool<<<Gg, 256>>>(bufB, batch, st2, g3, be3);            // 13
    k_head<<<1, 64>>>(attn_w, attn_b, fc1_w, fc1_b, fc2_w, fc2_b, out_w, out_b, out); // 14
}

// round 4
// speedup vs baseline: 1.4417x; 1.4417x over previous
#include <cuda_runtime.h>
#include <cuda_bf16.h>
#include <math.h>

#define Nn 100000
#define Ee 1600000
#define Gg 64

// ---------------- packed f32x2 helpers ----------------
#define PACK2(out, a, b) \
    asm("mov.b64 %0, {%1, %2};" : "=l"(out) : "f"(a), "f"(b))
#define FMA2(acc, a, b) \
    asm("fma.rn.f32x2 %0, %1, %2, %0;" : "+l"(acc) : "l"(a), "l"(b))

// ---------------- device scratch (static, no runtime allocation) ----------------
__device__ int   g_cnt[Nn];
__device__ int   g_rowptr[Nn + 1];
__device__ int   g_cursor[Nn];
__device__ int   g_cols[Ee];
__device__ float g_dis[Nn];
__device__ float g_bufA[Nn * 64];
__device__ float g_bufB[Nn * 64];
__device__ float g_stats[3 * 128];      // per layer: [0..H) sum, [H..2H) sumsq
__device__ int   g_bsum[256];           // scan partials
__device__ float g_pool[Gg * 33];       // per graph: sum[16], max[16], count

// ---------------- small utility kernels ----------------
__global__ void k_zero() {
    int i = blockIdx.x * 256 + threadIdx.x;
    if (i < Nn) g_cnt[i] = 0;
    if (i < 3 * 128) g_stats[i] = 0.f;
}
__global__ void k_hist(const int* __restrict__ dst) {
    int e = blockIdx.x * 256 + threadIdx.x;
    if (e < Ee) atomicAdd(&g_cnt[dst[e]], 1);
}
__global__ void k_dis() {
    int i = blockIdx.x * 256 + threadIdx.x;
    if (i < Nn) g_dis[i] = rsqrtf((float)(g_cnt[i] + 1));
}

#define SCAN_NB 196   // 196 * 512 = 100352 >= Nn

__global__ void k_scan1() {
    __shared__ int sh[512];
    int t = threadIdx.x, idx = blockIdx.x * 512 + t;
    sh[t] = (idx < Nn) ? g_cnt[idx] : 0;
    __syncthreads();
    for (int off = 256; off > 0; off >>= 1) {
        if (t < off) sh[t] += sh[t + off];
        __syncthreads();
    }
    if (t == 0) g_bsum[blockIdx.x] = sh[0];
}
__global__ void k_scan2() {
    __shared__ int sh[256];
    int t = threadIdx.x;
    int v = (t < SCAN_NB) ? g_bsum[t] : 0;
    sh[t] = v;
    __syncthreads();
    for (int off = 1; off < 256; off <<= 1) {
        int add = (t >= off) ? sh[t - off] : 0;
        __syncthreads();
        sh[t] += add;
        __syncthreads();
    }
    if (t < SCAN_NB) g_bsum[t] = sh[t] - v;   // exclusive
    if (t == 0) g_rowptr[Nn] = Ee;
}
__global__ void k_scan3() {
    __shared__ int sh[512];
    int t = threadIdx.x, idx = blockIdx.x * 512 + t;
    int v = (idx < Nn) ? g_cnt[idx] : 0;
    sh[t] = v;
    __syncthreads();
    for (int off = 1; off < 512; off <<= 1) {
        int add = (t >= off) ? sh[t - off] : 0;
        __syncthreads();
        sh[t] += add;
        __syncthreads();
    }
    if (idx < Nn) {
        int ex = g_bsum[blockIdx.x] + sh[t] - v;
        g_rowptr[idx] = ex;
        g_cursor[idx] = ex;
    }
}
__global__ void k_fill(const int* __restrict__ src, const int* __restrict__ dst) {
    int e = blockIdx.x * 256 + threadIdx.x;
    if (e < Ee) {
        int d = dst[e];
        int p = atomicAdd(&g_cursor[d], 1);
        g_cols[p] = src[e];
    }
}

// ---------------- GEMM (transposed-x register tile, packed f32x2 FMA) ----------------
// out[i,c] = dis[i] * sum_k f(h[i,k]) * W[k,c]
// f = identity (NORM=false) or BN-normalize + leaky relu (NORM=true).
// block = 128 threads, tile = 128 nodes. Thread owns 4 consecutive nodes
// ((tid&31)*4 ..+3) and C=H/4 channels (group tid>>5). x staged TRANSPOSED
// in smem (xt[k][node]) so 4 nodes come in one LDS.128; W chunk is
// warp-uniform broadcast. Per kk per thread: 2..5 LDS.128 per 32 FFMA2.
template <int K, int H, bool NORM>
__global__ void __launch_bounds__(128, 4) k_gemm(const float* __restrict__ h,
                                                 const float* __restrict__ W,
                                                 const float* __restrict__ stats,
                                                 const float* __restrict__ gamma,
                                                 const float* __restrict__ beta,
                                                 float* __restrict__ out) {
    constexpr int C = H / 4;              // channels per thread
    __shared__ float Wsm[16 * H];         // current k-chunk of W
    __shared__ float xt[16][128];         // transposed x chunk
    __shared__ float nsc[K], nsh[K];
    const int tid = threadIdx.x;
    const int base = blockIdx.x * 128;
    const int n0 = (tid & 31) * 4;        // first of 4 owned nodes (local)
    const int cg = tid >> 5;              // channel group 0..3
    const int cbase = cg * C;

    if (NORM) {
        for (int c = tid; c < K; c += 128) {
            float m = stats[c] * (1.0f / Nn);
            float var = stats[K + c] * (1.0f / Nn) - m * m;
            float rstd = rsqrtf(var + 1e-5f);
            float sc = rstd * gamma[c];
            nsc[c] = sc;
            nsh[c] = beta[c] - m * sc;
        }
        __syncthreads();
    }

    unsigned long long acc2[4][C / 2];
#pragma unroll
    for (int t = 0; t < 4; t++)
#pragma unroll
        for (int j = 0; j < C / 2; j++) acc2[t][j] = 0ull;

    const int myrow = base + tid;         // staging row for this thread

    for (int kc = 0; kc < K; kc += 16) {
        // stage W chunk [16][H]
        {
            const float4* Wg = reinterpret_cast<const float4*>(W + kc * H);
            float4* Ws = reinterpret_cast<float4*>(Wsm);
#pragma unroll
            for (int i = tid; i < 16 * H / 4; i += 128) Ws[i] = Wg[i];
        }
        // stage x chunk transposed: xt[kk][tid] = f(h[base+tid][kc+kk])
#pragma unroll
        for (int q = 0; q < 4; q++) {
            float4 v = make_float4(0.f, 0.f, 0.f, 0.f);
            if (myrow < Nn)
                v = *reinterpret_cast<const float4*>(h + (size_t)myrow * K + kc + q * 4);
            if (NORM) {
                int cb = kc + q * 4;
                v.x = v.x * nsc[cb + 0] + nsh[cb + 0]; v.x = v.x > 0.f ? v.x : 0.1f * v.x;
                v.y = v.y * nsc[cb + 1] + nsh[cb + 1]; v.y = v.y > 0.f ? v.y : 0.1f * v.y;
                v.z = v.z * nsc[cb + 2] + nsh[cb + 2]; v.z = v.z > 0.f ? v.z : 0.1f * v.z;
                v.w = v.w * nsc[cb + 3] + nsh[cb + 3]; v.w = v.w > 0.f ? v.w : 0.1f * v.w;
            }
            xt[q * 4 + 0][tid] = v.x;
            xt[q * 4 + 1][tid] = v.y;
            xt[q * 4 + 2][tid] = v.z;
            xt[q * 4 + 3][tid] = v.w;
        }
        __syncthreads();
#pragma unroll
        for (int kk = 0; kk < 16; kk++) {
            float4 xv = *reinterpret_cast<const float4*>(&xt[kk][n0]);
            unsigned long long x0, x1, x2, x3;
            PACK2(x0, xv.x, xv.x);
            PACK2(x1, xv.y, xv.y);
            PACK2(x2, xv.z, xv.z);
            PACK2(x3, xv.w, xv.w);
            const unsigned long long* w2 =
                reinterpret_cast<const unsigned long long*>(&Wsm[kk * H + cbase]);
#pragma unroll
            for (int j = 0; j < C / 2; j++) {
                unsigned long long w = w2[j];
                FMA2(acc2[0][j], x0, w);
                FMA2(acc2[1][j], x1, w);
                FMA2(acc2[2][j], x2, w);
                FMA2(acc2[3][j], x3, w);
            }
        }
        __syncthreads();
    }

    // epilogue: scale by dis[node], store C channels for each of 4 nodes
#pragma unroll
    for (int t = 0; t < 4; t++) {
        int node = base + n0 + t;
        if (node < Nn) {
            float dn = g_dis[node];
            const float* a = reinterpret_cast<const float*>(acc2[t]);
            float* o = out + (size_t)node * H + cbase;
#pragma unroll
            for (int j = 0; j < C / 4; j++) {
                float4 r;
                r.x = a[4 * j + 0] * dn;
                r.y = a[4 * j + 1] * dn;
                r.z = a[4 * j + 2] * dn;
                r.w = a[4 * j + 3] * dn;
                *reinterpret_cast<float4*>(o + 4 * j) = r;
            }
        }
    }
}

// ---------------- gather: pre[i] = dis[i]*(hws[i] + sum_{e:dst=i} hws[src]) + b ----
// one warp per node, grid-stride; scalar per-channel loads (round-2 form);
// fused BN sum/sumsq accumulation
template <int H>
__global__ void __launch_bounds__(256) k_gather(const float* __restrict__ hws,
                                                const float* __restrict__ b,
                                                float* __restrict__ pre,
                                                float* __restrict__ stats) {
    constexpr int NCH = (H >= 32) ? H / 32 : 1;
    const int lane = threadIdx.x & 31;
    const int warp = (blockIdx.x * blockDim.x + threadIdx.x) >> 5;
    const int nwarps = (gridDim.x * blockDim.x) >> 5;
    const bool act = (H >= 32) || (lane < H);

    int c[NCH];
#pragma unroll
    for (int j = 0; j < NCH; j++) c[j] = lane + 32 * j;

    float s_sum[NCH], s_sq[NCH];
#pragma unroll
    for (int j = 0; j < NCH; j++) { s_sum[j] = 0.f; s_sq[j] = 0.f; }

    for (int node = warp; node < Nn; node += nwarps) {
        int r0 = g_rowptr[node], r1 = g_rowptr[node + 1];
        float acc[NCH];
        if (act) {
#pragma unroll
            for (int j = 0; j < NCH; j++) acc[j] = hws[node * H + c[j]];
        } else {
#pragma unroll
            for (int j = 0; j < NCH; j++) acc[j] = 0.f;
        }
        int p = r0;
        for (; p + 4 <= r1; p += 4) {
            int s0 = g_cols[p], s1 = g_cols[p + 1], s2 = g_cols[p + 2], s3 = g_cols[p + 3];
            if (act) {
#pragma unroll
                for (int j = 0; j < NCH; j++) {
                    float v0 = hws[s0 * H + c[j]];
                    float v1 = hws[s1 * H + c[j]];
                    float v2 = hws[s2 * H + c[j]];
                    float v3 = hws[s3 * H + c[j]];
                    acc[j] += (v0 + v1) + (v2 + v3);
                }
            }
        }
        for (; p < r1; p++) {
            int s = g_cols[p];
            if (act) {
#pragma unroll
                for (int j = 0; j < NCH; j++) acc[j] += hws[s * H + c[j]];
            }
        }
        if (act) {
            float dn = g_dis[node];
#pragma unroll
            for (int j = 0; j < NCH; j++) {
                float v = dn * acc[j] + b[c[j]];
                pre[node * H + c[j]] = v;
                s_sum[j] += v;
                s_sq[j] += v * v;
            }
        }
    }
    if (act) {
#pragma unroll
        for (int j = 0; j < NCH; j++) {
            atomicAdd(&stats[c[j]], s_sum[j]);
            atomicAdd(&stats[H + c[j]], s_sq[j]);
        }
    }
}

// ---------------- pooling: per-graph sum/max/count over normalized x3 [N,16] ----------------
__device__ __forceinline__ int lower_bound_batch(const int* __restrict__ batch, int g) {
    int lo = 0, hi = Nn;
    while (lo < hi) {
        int m = (lo + hi) >> 1;
        if (batch[m] < g) lo = m + 1; else hi = m;
    }
    return lo;
}

__global__ void k_pool(const float* __restrict__ x3, const int* __restrict__ batch,
                       const float* __restrict__ stats,
                       const float* __restrict__ gamma, const float* __restrict__ beta) {
    __shared__ int ss, se;
    __shared__ float ssum[256], smax[256];
    int g = blockIdx.x, t = threadIdx.x;
    if (t == 0) { ss = lower_bound_batch(batch, g); se = lower_bound_batch(batch, g + 1); }
    __syncthreads();
    int s = ss, e = se;
    int c = t & 15;
    // per-channel BN scale/shift (layer 3)
    float m = stats[c] * (1.0f / Nn);
    float var = stats[16 + c] * (1.0f / Nn) - m * m;
    float rstd = rsqrtf(var + 1e-5f);
    float sc = rstd * gamma[c];
    float sh = beta[c] - m * sc;

    float sum = 0.f, mx = -3.402823466e+38f;
    for (int r = s + (t >> 4); r < e; r += 16) {
        float v = x3[r * 16 + c] * sc + sh;
        v = v > 0.f ? v : 0.1f * v;
        sum += v;
        mx = fmaxf(mx, v);
    }
    ssum[t] = sum; smax[t] = mx;
    __syncthreads();
    for (int off = 128; off >= 16; off >>= 1) {
        if (t < off) { ssum[t] += ssum[t + off]; smax[t] = fmaxf(smax[t], smax[t + off]); }
        __syncthreads();
    }
    if (t < 16) { g_pool[g * 33 + t] = ssum[t]; g_pool[g * 33 + 16 + t] = smax[t]; }
    if (t == 0) g_pool[g * 33 + 32] = (float)(e - s);
}

// ---------------- head: attention pooling + MLP + sigmoid ----------------
__global__ void k_head(const float* __restrict__ attn_w, const float* __restrict__ attn_b,
                       const float* __restrict__ fc1_w, const float* __restrict__ fc1_b,
                       const float* __restrict__ fc2_w, const float* __restrict__ fc2_b,
                       const float* __restrict__ out_w, const float* __restrict__ out_b,
                       float* __restrict__ out) {
    int g = threadIdx.x;
    if (g >= Gg) return;
    float sm[16], mx[16], mean[16];
    float cnt = g_pool[g * 33 + 32];
    float inv = 1.0f / fmaxf(cnt, 1.0f);
#pragma unroll
    for (int k = 0; k < 16; k++) {
        sm[k] = g_pool[g * 33 + k];
        mx[k] = g_pool[g * 33 + 16 + k];
        mean[k] = sm[k] * inv;
    }
    float z[3];
#pragma unroll
    for (int j = 0; j < 3; j++) z[j] = attn_b[j];
#pragma unroll
    for (int k = 0; k < 16; k++) {
#pragma unroll
        for (int j = 0; j < 3; j++) {
            z[j] += mean[k] * attn_w[k * 3 + j]
                  + mx[k]   * attn_w[(16 + k) * 3 + j]
                  + sm[k]   * attn_w[(32 + k) * 3 + j];
        }
    }
    float zm = fmaxf(z[0], fmaxf(z[1], z[2]));
    float e0 = expf(z[0] - zm), e1 = expf(z[1] - zm), e2 = expf(z[2] - zm);
    float is = 1.f / (e0 + e1 + e2);
    float a0 = e0 * is, a1 = e1 * is, a2 = e2 * is;
    float xg[16];
#pragma unroll
    for (int k = 0; k < 16; k++) xg[k] = a0 * mean[k] + a1 * mx[k] + a2 * sm[k];
    float y1[16];
#pragma unroll
    for (int j = 0; j < 16; j++) {
        float acc = fc1_b[j];
#pragma unroll
        for (int k = 0; k < 16; k++) acc += xg[k] * fc1_w[k * 16 + j];
        y1[j] = acc > 0.f ? acc : 0.1f * acc;
    }
    float y2[8];
#pragma unroll
    for (int j = 0; j < 8; j++) {
        float acc = fc2_b[j];
#pragma unroll
        for (int k = 0; k < 16; k++) acc += y1[k] * fc2_w[k * 8 + j];
        y2[j] = acc > 0.f ? acc : 0.1f * acc;
    }
    float o = out_b[0];
#pragma unroll
    for (int k = 0; k < 8; k++) o += y2[k] * out_w[k];
    out[g] = 1.f / (1.f + expf(-o));
}

// ---------------- host launch ----------------
extern "C" void kernel_launch(void* const* d_in, const int* in_sizes, int n_in,
                              void* d_out, int out_size) {
    const float* x      = (const float*)d_in[0];
    const float* W1     = (const float*)d_in[1];
    const float* b1     = (const float*)d_in[2];
    const float* W2     = (const float*)d_in[3];
    const float* b2     = (const float*)d_in[4];
    const float* W3     = (const float*)d_in[5];
    const float* b3     = (const float*)d_in[6];
    const float* g1     = (const float*)d_in[7];
    const float* be1    = (const float*)d_in[8];
    const float* g2     = (const float*)d_in[9];
    const float* be2    = (const float*)d_in[10];
    const float* g3     = (const float*)d_in[11];
    const float* be3    = (const float*)d_in[12];
    const float* attn_w = (const float*)d_in[13];
    const float* attn_b = (const float*)d_in[14];
    const float* fc1_w  = (const float*)d_in[15];
    const float* fc1_b  = (const float*)d_in[16];
    const float* fc2_w  = (const float*)d_in[17];
    const float* fc2_b  = (const float*)d_in[18];
    const float* out_w  = (const float*)d_in[19];
    const float* out_b  = (const float*)d_in[20];
    const int*   ei     = (const int*)d_in[21];
    const int*   batch  = (const int*)d_in[22];

    const int* src = ei;
    const int* dst = ei + Ee;
    float* out = (float*)d_out;

    void *pA = nullptr, *pB = nullptr, *pS = nullptr;
    cudaGetSymbolAddress(&pA, g_bufA);
    cudaGetSymbolAddress(&pB, g_bufB);
    cudaGetSymbolAddress(&pS, g_stats);
    float* bufA = (float*)pA;
    float* bufB = (float*)pB;
    float* st0 = (float*)pS;          // layer1 stats (sum[64], sq[64])
    float* st1 = st0 + 128;           // layer2 stats (sum[32], sq[32])
    float* st2 = st0 + 256;           // layer3 stats (sum[16], sq[16])

    const int gemm_grid = (Nn + 127) / 128;   // 782
    const int gather_grid = 1184;             // 148 SMs * 8 blocks

    // degree + dis first, so GEMM1 (profiled slot 3) only needs dis
    k_zero<<<(Nn + 255) / 256, 256>>>();                       // 0
    k_hist<<<(Ee + 255) / 256, 256>>>(dst);                    // 1
    k_dis<<<(Nn + 255) / 256, 256>>>();                        // 2
    k_gemm<128, 64, false><<<gemm_grid, 128>>>(x, W1, nullptr, nullptr, nullptr, bufA); // 3
    k_scan1<<<SCAN_NB, 512>>>();                               // 4
    k_scan2<<<1, 256>>>();                                     // 5
    k_scan3<<<SCAN_NB, 512>>>();                               // 6
    k_fill<<<(Ee + 255) / 256, 256>>>(src, dst);               // 7

    // Layer 1 aggregate
    k_gather<64><<<gather_grid, 256>>>(bufA, b1, bufB, st0);   // 8

    // Layer 2: 64 -> 32 (BN1 + lrelu fused into GEMM load)
    k_gemm<64, 32, true><<<gemm_grid, 128>>>(bufB, W2, st0, g1, be1, bufA);   // 9
    k_gather<32><<<gather_grid, 256>>>(bufA, b2, bufB, st1);   // 10

    // Layer 3: 32 -> 16 (BN2 + lrelu fused into GEMM load)
    k_gemm<32, 16, true><<<gemm_grid, 128>>>(bufB, W3, st1, g2, be2, bufA);   // 11
    k_gather<16><<<gather_grid, 256>>>(bufA, b3, bufB, st2);   // 12

    // Pool (BN3 + lrelu fused) + head
    k_pool<<<Gg, 256>>>(bufB, batch, st2, g3, be3);            // 13
    k_head<<<1, 64>>>(attn_w, attn_b, fc1_w, fc1_b, fc2_w, fc2_b, out_w, out_b, out); // 14
}

// round 5
// speedup vs baseline: 1.5057x; 1.0444x over previous
#include <cuda_runtime.h>
#include <cuda_bf16.h>
#include <math.h>

#define Nn 100000
#define Ee 1600000
#define Gg 64

// ---------------- packed f32x2 helpers ----------------
#define PACK2(out, a, b) \
    asm("mov.b64 %0, {%1, %2};" : "=l"(out) : "f"(a), "f"(b))
#define FMA2(acc, a, b) \
    asm("fma.rn.f32x2 %0, %1, %2, %0;" : "+l"(acc) : "l"(a), "l"(b))

// ---------------- device scratch (static, no runtime allocation) ----------------
__device__ int   g_cnt[Nn];
__device__ int   g_rowptr[Nn + 1];
__device__ int   g_cursor[Nn];
__device__ int   g_cols[Ee];
__device__ float g_dis[Nn];
__device__ float g_bufA[Nn * 64];
__device__ float g_bufB[Nn * 64];
__device__ float g_stats[3 * 128];      // per layer: [0..H) sum, [H..2H) sumsq
__device__ int   g_bsum[256];           // scan partials
__device__ float g_pool[Gg * 33];       // per graph: sum[16], max[16], count

// ---------------- small utility kernels ----------------
__global__ void k_zero() {
    int i = blockIdx.x * 256 + threadIdx.x;
    if (i < Nn) g_cnt[i] = 0;
    if (i < 3 * 128) g_stats[i] = 0.f;
}
__global__ void k_hist(const int* __restrict__ dst) {
    int e = blockIdx.x * 256 + threadIdx.x;
    if (e < Ee) atomicAdd(&g_cnt[dst[e]], 1);
}
__global__ void k_dis() {
    int i = blockIdx.x * 256 + threadIdx.x;
    if (i < Nn) g_dis[i] = rsqrtf((float)(g_cnt[i] + 1));
}

#define SCAN_NB 196   // 196 * 512 = 100352 >= Nn

__global__ void k_scan1() {
    __shared__ int sh[512];
    int t = threadIdx.x, idx = blockIdx.x * 512 + t;
    sh[t] = (idx < Nn) ? g_cnt[idx] : 0;
    __syncthreads();
    for (int off = 256; off > 0; off >>= 1) {
        if (t < off) sh[t] += sh[t + off];
        __syncthreads();
    }
    if (t == 0) g_bsum[blockIdx.x] = sh[0];
}
__global__ void k_scan2() {
    __shared__ int sh[256];
    int t = threadIdx.x;
    int v = (t < SCAN_NB) ? g_bsum[t] : 0;
    sh[t] = v;
    __syncthreads();
    for (int off = 1; off < 256; off <<= 1) {
        int add = (t >= off) ? sh[t - off] : 0;
        __syncthreads();
        sh[t] += add;
        __syncthreads();
    }
    if (t < SCAN_NB) g_bsum[t] = sh[t] - v;   // exclusive
    if (t == 0) g_rowptr[Nn] = Ee;
}
__global__ void k_scan3() {
    __shared__ int sh[512];
    int t = threadIdx.x, idx = blockIdx.x * 512 + t;
    int v = (idx < Nn) ? g_cnt[idx] : 0;
    sh[t] = v;
    __syncthreads();
    for (int off = 1; off < 512; off <<= 1) {
        int add = (t >= off) ? sh[t - off] : 0;
        __syncthreads();
        sh[t] += add;
        __syncthreads();
    }
    if (idx < Nn) {
        int ex = g_bsum[blockIdx.x] + sh[t] - v;
        g_rowptr[idx] = ex;
        g_cursor[idx] = ex;
    }
}
__global__ void k_fill(const int* __restrict__ src, const int* __restrict__ dst) {
    int e = blockIdx.x * 256 + threadIdx.x;
    if (e < Ee) {
        int d = dst[e];
        int p = atomicAdd(&g_cursor[d], 1);
        g_cols[p] = src[e];
    }
}

// ---------------- GEMM (transposed-x register tile, packed f32x2 FMA) ----------------
// out[i,c] = dis[i] * sum_k f(h[i,k]) * W[k,c]
// f = identity (NORM=false) or BN-normalize + leaky relu (NORM=true).
// block = 128 threads, tile = 128 nodes. Thread owns 4 consecutive nodes
// ((tid&31)*4 ..+3) and C=H/4 channels (group tid>>5). x staged TRANSPOSED
// in smem (xt[k][node]); W chunk read as warp-uniform 16B broadcasts.
template <int K, int H, bool NORM>
__global__ void __launch_bounds__(128, 4) k_gemm(const float* __restrict__ h,
                                                 const float* __restrict__ W,
                                                 const float* __restrict__ stats,
                                                 const float* __restrict__ gamma,
                                                 const float* __restrict__ beta,
                                                 float* __restrict__ out) {
    constexpr int C = H / 4;              // channels per thread
    __shared__ float Wsm[16 * H];         // current k-chunk of W
    __shared__ float xt[16][128];         // transposed x chunk
    __shared__ float nsc[K], nsh[K];
    const int tid = threadIdx.x;
    const int base = blockIdx.x * 128;
    const int n0 = (tid & 31) * 4;        // first of 4 owned nodes (local)
    const int cg = tid >> 5;              // channel group 0..3
    const int cbase = cg * C;

    if (NORM) {
        for (int c = tid; c < K; c += 128) {
            float m = stats[c] * (1.0f / Nn);
            float var = stats[K + c] * (1.0f / Nn) - m * m;
            float rstd = rsqrtf(var + 1e-5f);
            float sc = rstd * gamma[c];
            nsc[c] = sc;
            nsh[c] = beta[c] - m * sc;
        }
        __syncthreads();
    }

    unsigned long long acc2[4][C / 2];
#pragma unroll
    for (int t = 0; t < 4; t++)
#pragma unroll
        for (int j = 0; j < C / 2; j++) acc2[t][j] = 0ull;

    const int myrow = base + tid;         // staging row for this thread

    for (int kc = 0; kc < K; kc += 16) {
        // stage W chunk [16][H]
        {
            const float4* Wg = reinterpret_cast<const float4*>(W + kc * H);
            float4* Ws = reinterpret_cast<float4*>(Wsm);
#pragma unroll
            for (int i = tid; i < 16 * H / 4; i += 128) Ws[i] = Wg[i];
        }
        // stage x chunk transposed: xt[kk][tid] = f(h[base+tid][kc+kk])
#pragma unroll
        for (int q = 0; q < 4; q++) {
            float4 v = make_float4(0.f, 0.f, 0.f, 0.f);
            if (myrow < Nn)
                v = *reinterpret_cast<const float4*>(h + (size_t)myrow * K + kc + q * 4);
            if (NORM) {
                int cb = kc + q * 4;
                v.x = v.x * nsc[cb + 0] + nsh[cb + 0]; v.x = v.x > 0.f ? v.x : 0.1f * v.x;
                v.y = v.y * nsc[cb + 1] + nsh[cb + 1]; v.y = v.y > 0.f ? v.y : 0.1f * v.y;
                v.z = v.z * nsc[cb + 2] + nsh[cb + 2]; v.z = v.z > 0.f ? v.z : 0.1f * v.z;
                v.w = v.w * nsc[cb + 3] + nsh[cb + 3]; v.w = v.w > 0.f ? v.w : 0.1f * v.w;
            }
            xt[q * 4 + 0][tid] = v.x;
            xt[q * 4 + 1][tid] = v.y;
            xt[q * 4 + 2][tid] = v.z;
            xt[q * 4 + 3][tid] = v.w;
        }
        __syncthreads();
#pragma unroll
        for (int kk = 0; kk < 16; kk++) {
            float4 xv = *reinterpret_cast<const float4*>(&xt[kk][n0]);
            unsigned long long x0, x1, x2, x3;
            PACK2(x0, xv.x, xv.x);
            PACK2(x1, xv.y, xv.y);
            PACK2(x2, xv.z, xv.z);
            PACK2(x3, xv.w, xv.w);
            const ulonglong2* w2 =
                reinterpret_cast<const ulonglong2*>(&Wsm[kk * H + cbase]);
#pragma unroll
            for (int j = 0; j < C / 4; j++) {
                ulonglong2 w = w2[j];
                FMA2(acc2[0][2 * j + 0], x0, w.x);
                FMA2(acc2[0][2 * j + 1], x0, w.y);
                FMA2(acc2[1][2 * j + 0], x1, w.x);
                FMA2(acc2[1][2 * j + 1], x1, w.y);
                FMA2(acc2[2][2 * j + 0], x2, w.x);
                FMA2(acc2[2][2 * j + 1], x2, w.y);
                FMA2(acc2[3][2 * j + 0], x3, w.x);
                FMA2(acc2[3][2 * j + 1], x3, w.y);
            }
        }
        __syncthreads();
    }

    // epilogue: scale by dis[node], store C channels for each of 4 nodes
#pragma unroll
    for (int t = 0; t < 4; t++) {
        int node = base + n0 + t;
        if (node < Nn) {
            float dn = g_dis[node];
            const float* a = reinterpret_cast<const float*>(acc2[t]);
            float* o = out + (size_t)node * H + cbase;
#pragma unroll
            for (int j = 0; j < C / 4; j++) {
                float4 r;
                r.x = a[4 * j + 0] * dn;
                r.y = a[4 * j + 1] * dn;
                r.z = a[4 * j + 2] * dn;
                r.w = a[4 * j + 3] * dn;
                *reinterpret_cast<float4*>(o + 4 * j) = r;
            }
        }
    }
}

// ---------------- gather: pre[i] = dis[i]*(hws[i] + sum_{e:dst=i} hws[src]) + b ----
// one warp per node, grid-stride; fused BN sum/sumsq accumulation
template <int H>
__global__ void __launch_bounds__(256) k_gather(const float* __restrict__ hws,
                                                const float* __restrict__ b,
                                                float* __restrict__ pre,
                                                float* __restrict__ stats) {
    constexpr int NCH = (H >= 32) ? H / 32 : 1;
    const int lane = threadIdx.x & 31;
    const int warp = (blockIdx.x * blockDim.x + threadIdx.x) >> 5;
    const int nwarps = (gridDim.x * blockDim.x) >> 5;
    const bool act = (H >= 32) || (lane < H);

    int c[NCH];
#pragma unroll
    for (int j = 0; j < NCH; j++) c[j] = lane + 32 * j;

    float s_sum[NCH], s_sq[NCH];
#pragma unroll
    for (int j = 0; j < NCH; j++) { s_sum[j] = 0.f; s_sq[j] = 0.f; }

    for (int node = warp; node < Nn; node += nwarps) {
        int r0 = g_rowptr[node], r1 = g_rowptr[node + 1];
        float acc[NCH];
        if (act) {
#pragma unroll
            for (int j = 0; j < NCH; j++) acc[j] = hws[node * H + c[j]];
        } else {
#pragma unroll
            for (int j = 0; j < NCH; j++) acc[j] = 0.f;
        }
        int p = r0;
        for (; p + 4 <= r1; p += 4) {
            int s0 = g_cols[p], s1 = g_cols[p + 1], s2 = g_cols[p + 2], s3 = g_cols[p + 3];
            if (act) {
#pragma unroll
                for (int j = 0; j < NCH; j++) {
                    float v0 = hws[s0 * H + c[j]];
                    float v1 = hws[s1 * H + c[j]];
                    float v2 = hws[s2 * H + c[j]];
                    float v3 = hws[s3 * H + c[j]];
                    acc[j] += (v0 + v1) + (v2 + v3);
                }
            }
        }
        for (; p < r1; p++) {
            int s = g_cols[p];
            if (act) {
#pragma unroll
                for (int j = 0; j < NCH; j++) acc[j] += hws[s * H + c[j]];
            }
        }
        if (act) {
            float dn = g_dis[node];
#pragma unroll
            for (int j = 0; j < NCH; j++) {
                float v = dn * acc[j] + b[c[j]];
                pre[node * H + c[j]] = v;
                s_sum[j] += v;
                s_sq[j] += v * v;
            }
        }
    }
    if (act) {
#pragma unroll
        for (int j = 0; j < NCH; j++) {
            atomicAdd(&stats[c[j]], s_sum[j]);
            atomicAdd(&stats[H + c[j]], s_sq[j]);
        }
    }
}

// ---------------- pooling: per-graph sum/max/count over normalized x3 [N,16] ----------------
__device__ __forceinline__ int lower_bound_batch(const int* __restrict__ batch, int g) {
    int lo = 0, hi = Nn;
    while (lo < hi) {
        int m = (lo + hi) >> 1;
        if (batch[m] < g) lo = m + 1; else hi = m;
    }
    return lo;
}

__global__ void k_pool(const float* __restrict__ x3, const int* __restrict__ batch,
                       const float* __restrict__ stats,
                       const float* __restrict__ gamma, const float* __restrict__ beta) {
    __shared__ int ss, se;
    __shared__ float ssum[256], smax[256];
    int g = blockIdx.x, t = threadIdx.x;
    if (t == 0) { ss = lower_bound_batch(batch, g); se = lower_bound_batch(batch, g + 1); }
    __syncthreads();
    int s = ss, e = se;
    int c = t & 15;
    // per-channel BN scale/shift (layer 3)
    float m = stats[c] * (1.0f / Nn);
    float var = stats[16 + c] * (1.0f / Nn) - m * m;
    float rstd = rsqrtf(var + 1e-5f);
    float sc = rstd * gamma[c];
    float sh = beta[c] - m * sc;

    float sum = 0.f, mx = -3.402823466e+38f;
    for (int r = s + (t >> 4); r < e; r += 16) {
        float v = x3[r * 16 + c] * sc + sh;
        v = v > 0.f ? v : 0.1f * v;
        sum += v;
        mx = fmaxf(mx, v);
    }
    ssum[t] = sum; smax[t] = mx;
    __syncthreads();
    for (int off = 128; off >= 16; off >>= 1) {
        if (t < off) { ssum[t] += ssum[t + off]; smax[t] = fmaxf(smax[t], smax[t + off]); }
        __syncthreads();
    }
    if (t < 16) { g_pool[g * 33 + t] = ssum[t]; g_pool[g * 33 + 16 + t] = smax[t]; }
    if (t == 0) g_pool[g * 33 + 32] = (float)(e - s);
}

// ---------------- head: attention pooling + MLP + sigmoid ----------------
__global__ void k_head(const float* __restrict__ attn_w, const float* __restrict__ attn_b,
                       const float* __restrict__ fc1_w, const float* __restrict__ fc1_b,
                       const float* __restrict__ fc2_w, const float* __restrict__ fc2_b,
                       const float* __restrict__ out_w, const float* __restrict__ out_b,
                       float* __restrict__ out) {
    int g = threadIdx.x;
    if (g >= Gg) return;
    float sm[16], mx[16], mean[16];
    float cnt = g_pool[g * 33 + 32];
    float inv = 1.0f / fmaxf(cnt, 1.0f);
#pragma unroll
    for (int k = 0; k < 16; k++) {
        sm[k] = g_pool[g * 33 + k];
        mx[k] = g_pool[g * 33 + 16 + k];
        mean[k] = sm[k] * inv;
    }
    float z[3];
#pragma unroll
    for (int j = 0; j < 3; j++) z[j] = attn_b[j];
#pragma unroll
    for (int k = 0; k < 16; k++) {
#pragma unroll
        for (int j = 0; j < 3; j++) {
            z[j] += mean[k] * attn_w[k * 3 + j]
                  + mx[k]   * attn_w[(16 + k) * 3 + j]
                  + sm[k]   * attn_w[(32 + k) * 3 + j];
        }
    }
    float zm = fmaxf(z[0], fmaxf(z[1], z[2]));
    float e0 = expf(z[0] - zm), e1 = expf(z[1] - zm), e2 = expf(z[2] - zm);
    float is = 1.f / (e0 + e1 + e2);
    float a0 = e0 * is, a1 = e1 * is, a2 = e2 * is;
    float xg[16];
#pragma unroll
    for (int k = 0; k < 16; k++) xg[k] = a0 * mean[k] + a1 * mx[k] + a2 * sm[k];
    float y1[16];
#pragma unroll
    for (int j = 0; j < 16; j++) {
        float acc = fc1_b[j];
#pragma unroll
        for (int k = 0; k < 16; k++) acc += xg[k] * fc1_w[k * 16 + j];
        y1[j] = acc > 0.f ? acc : 0.1f * acc;
    }
    float y2[8];
#pragma unroll
    for (int j = 0; j < 8; j++) {
        float acc = fc2_b[j];
#pragma unroll
        for (int k = 0; k < 16; k++) acc += y1[k] * fc2_w[k * 8 + j];
        y2[j] = acc > 0.f ? acc : 0.1f * acc;
    }
    float o = out_b[0];
#pragma unroll
    for (int k = 0; k < 8; k++) o += y2[k] * out_w[k];
    out[g] = 1.f / (1.f + expf(-o));
}

// ---------------- host launch ----------------
extern "C" void kernel_launch(void* const* d_in, const int* in_sizes, int n_in,
                              void* d_out, int out_size) {
    const float* x      = (const float*)d_in[0];
    const float* W1     = (const float*)d_in[1];
    const float* b1     = (const float*)d_in[2];
    const float* W2     = (const float*)d_in[3];
    const float* b2     = (const float*)d_in[4];
    const float* W3     = (const float*)d_in[5];
    const float* b3     = (const float*)d_in[6];
    const float* g1     = (const float*)d_in[7];
    const float* be1    = (const float*)d_in[8];
    const float* g2     = (const float*)d_in[9];
    const float* be2    = (const float*)d_in[10];
    const float* g3     = (const float*)d_in[11];
    const float* be3    = (const float*)d_in[12];
    const float* attn_w = (const float*)d_in[13];
    const float* attn_b = (const float*)d_in[14];
    const float* fc1_w  = (const float*)d_in[15];
    const float* fc1_b  = (const float*)d_in[16];
    const float* fc2_w  = (const float*)d_in[17];
    const float* fc2_b  = (const float*)d_in[18];
    const float* out_w  = (const float*)d_in[19];
    const float* out_b  = (const float*)d_in[20];
    const int*   ei     = (const int*)d_in[21];
    const int*   batch  = (const int*)d_in[22];

    const int* src = ei;
    const int* dst = ei + Ee;
    float* out = (float*)d_out;

    void *pA = nullptr, *pB = nullptr, *pS = nullptr;
    cudaGetSymbolAddress(&pA, g_bufA);
    cudaGetSymbolAddress(&pB, g_bufB);
    cudaGetSymbolAddress(&pS, g_stats);
    float* bufA = (float*)pA;
    float* bufB = (float*)pB;
    float* st0 = (float*)pS;          // layer1 stats (sum[64], sq[64])
    float* st1 = st0 + 128;           // layer2 stats (sum[32], sq[32])
    float* st2 = st0 + 256;           // layer3 stats (sum[16], sq[16])

    // side stream + events for overlapping GEMM1 with the CSR scan/fill chain.
    // Created once; the captured work is identical on every call.
    static cudaStream_t sB = nullptr;
    static cudaEvent_t evFork = nullptr, evJoin = nullptr;
    if (sB == nullptr) {
        cudaStreamCreateWithFlags(&sB, cudaStreamNonBlocking);
        cudaEventCreateWithFlags(&evFork, cudaEventDisableTiming);
        cudaEventCreateWithFlags(&evJoin, cudaEventDisableTiming);
    }

    const int gemm_grid = (Nn + 127) / 128;   // 782
    const int gather_grid = 1184;             // 148 SMs * 8 blocks

    // ---- prefix: degree + dis (needed by both branches) ----
    k_zero<<<(Nn + 255) / 256, 256>>>();
    k_hist<<<(Ee + 255) / 256, 256>>>(dst);
    k_dis<<<(Nn + 255) / 256, 256>>>();
    cudaEventRecord(evFork, 0);

    // ---- branch B: GEMM1 (independent of scan/fill) ----
    cudaStreamWaitEvent(sB, evFork, 0);
    k_gemm<128, 64, false><<<gemm_grid, 128, 0, sB>>>(x, W1, nullptr, nullptr, nullptr, bufA);
    cudaEventRecord(evJoin, sB);

    // ---- branch A (main stream): CSR scan + fill ----
    k_scan1<<<SCAN_NB, 512>>>();
    k_scan2<<<1, 256>>>();
    k_scan3<<<SCAN_NB, 512>>>();
    k_fill<<<(Ee + 255) / 256, 256>>>(src, dst);

    // ---- join: gather needs CSR + GEMM1 output ----
    cudaStreamWaitEvent(0, evJoin, 0);
    k_gather<64><<<gather_grid, 256>>>(bufA, b1, bufB, st0);

    // Layer 2: 64 -> 32 (BN1 + lrelu fused into GEMM load)
    k_gemm<64, 32, true><<<gemm_grid, 128>>>(bufB, W2, st0, g1, be1, bufA);
    k_gather<32><<<gather_grid, 256>>>(bufA, b2, bufB, st1);

    // Layer 3: 32 -> 16 (BN2 + lrelu fused into GEMM load)
    k_gemm<32, 16, true><<<gemm_grid, 128>>>(bufB, W3, st1, g2, be2, bufA);
    k_gather<16><<<gather_grid, 256>>>(bufA, b3, bufB, st2);

    // Pool (BN3 + lrelu fused) + head
    k_pool<<<Gg, 256>>>(bufB, batch, st2, g3, be3);
    k_head<<<1, 64>>>(attn_w, attn_b, fc1_w, fc1_b, fc2_w, fc2_b, out_w, out_b, out);
}